// round 10
// baseline (speedup 1.0000x reference)
#include <cuda_runtime.h>
#include <cuda_fp16.h>
#include <cstdint>

#define NN 100000
#define INF_ 128
#define OUTF 64
#define NE 1600000
#define NCHUNK ((NN + 511) / 512)   // 196

// Static device scratch (allocation-free per harness rules)
__device__ __half g_support_h[(size_t)NN * OUTF];  // 12.8 MB (fp16 gather path)
__device__ int    g_counts[NN];
__device__ int    g_rowstart[NN];
__device__ int    g_cursor[NN];
__device__ int    g_chunkagg[NCHUNK];
__device__ int    g_chunkpfx[NCHUNK];
__device__ int    g_chunkflag[NCHUNK];             // 0=none 1=agg 2=pfx
__device__ int2   g_packed[NE];                    // 12.8 MB (col, val-bits) by row

// ---------------------------------------------------------------------------
// support = X @ W.  Tiled fp32 SIMT GEMM; epilogue stores fp16.
// Also zeroes g_counts and scan flags (hist/scan launch after in stream order).
// ---------------------------------------------------------------------------
__global__ __launch_bounds__(256, 2)
void gemm_kernel(const float* __restrict__ x, const float* __restrict__ w, int n) {
    __shared__ float xs[64][132];
    __shared__ float ws[128][68];

    const int tid  = threadIdx.x;
    const int brow = blockIdx.x * 64;

    // Fused: zero histogram counters + scan flags
    {
        int gi = blockIdx.x * 256 + tid;
        if (gi < NN) g_counts[gi] = 0;
        if (gi < NCHUNK) g_chunkflag[gi] = 0;
    }

#pragma unroll
    for (int it = 0; it < 8; it++) {
        int i = tid + it * 256;
        int k = i >> 4;
        int c = (i & 15) << 2;
        float4 v = *(const float4*)&w[k * OUTF + c];
        *(float4*)&ws[k][c] = v;
    }
#pragma unroll
    for (int it = 0; it < 8; it++) {
        int i = tid + it * 256;
        int r = i >> 5;
        int k = (i & 31) << 2;
        int grow = brow + r;
        float4 v = make_float4(0.f, 0.f, 0.f, 0.f);
        if (grow < n) v = *(const float4*)&x[(size_t)grow * INF_ + k];
        *(float4*)&xs[r][k] = v;
    }
    __syncthreads();

    const int r0 = (tid >> 4) << 2;
    const int c0 = (tid & 15) << 2;

    float acc[4][4] = {};
#pragma unroll 4
    for (int k = 0; k < 128; k++) {
        float a0 = xs[r0 + 0][k];
        float a1 = xs[r0 + 1][k];
        float a2 = xs[r0 + 2][k];
        float a3 = xs[r0 + 3][k];
        float4 b = *(float4*)&ws[k][c0];
        acc[0][0] += a0 * b.x; acc[0][1] += a0 * b.y; acc[0][2] += a0 * b.z; acc[0][3] += a0 * b.w;
        acc[1][0] += a1 * b.x; acc[1][1] += a1 * b.y; acc[1][2] += a1 * b.z; acc[1][3] += a1 * b.w;
        acc[2][0] += a2 * b.x; acc[2][1] += a2 * b.y; acc[2][2] += a2 * b.z; acc[2][3] += a2 * b.w;
        acc[3][0] += a3 * b.x; acc[3][1] += a3 * b.y; acc[3][2] += a3 * b.z; acc[3][3] += a3 * b.w;
    }

#pragma unroll
    for (int i = 0; i < 4; i++) {
        int grow = brow + r0 + i;
        if (grow < n) {
            __half2 h0 = __floats2half2_rn(acc[i][0], acc[i][1]);
            __half2 h1 = __floats2half2_rn(acc[i][2], acc[i][3]);
            uint2 u = make_uint2(*(unsigned*)&h0, *(unsigned*)&h1);
            *(uint2*)&g_support_h[(size_t)grow * OUTF + c0] = u;
        }
    }
}

// ---------------------------------------------------------------------------
// Build phase: counting sort of edges by destination row
// ---------------------------------------------------------------------------
__global__ void hist_kernel(const int* __restrict__ erow) {
    int e = blockIdx.x * blockDim.x + threadIdx.x;
    if (e < NE) atomicAdd(&g_counts[__ldg(&erow[e])], 1);
}

// Single-pass exclusive scan of g_counts with decoupled lookback.
__global__ __launch_bounds__(512)
void scan_kernel() {
    __shared__ int s[512];
    __shared__ int sbase;
    int t = threadIdx.x, b = blockIdx.x;
    int i = b * 512 + t;
    int v = (i < NN) ? g_counts[i] : 0;
    s[t] = v;
    __syncthreads();
#pragma unroll
    for (int off = 1; off < 512; off <<= 1) {
        int a = (t >= off) ? s[t - off] : 0;
        __syncthreads();
        s[t] += a;
        __syncthreads();
    }
    int agg = s[511];

    if (t == 0) {
        if (b == 0) {
            sbase = 0;
            g_chunkpfx[0] = agg;
            __threadfence();
            atomicExch(&g_chunkflag[0], 2);
        } else {
            g_chunkagg[b] = agg;
            __threadfence();
            atomicExch(&g_chunkflag[b], 1);
            // lookback
            int run = 0;
            for (int c = b - 1; c >= 0; ) {
                int f;
                do { f = *(volatile int*)&g_chunkflag[c]; } while (f == 0);
                __threadfence();
                if (f == 2) { run += *(volatile int*)&g_chunkpfx[c]; break; }
                run += *(volatile int*)&g_chunkagg[c];
                c--;
            }
            sbase = run;
            g_chunkpfx[b] = run + agg;
            __threadfence();
            atomicExch(&g_chunkflag[b], 2);
        }
    }
    __syncthreads();

    if (i < NN) {
        int excl = s[t] - v + sbase;
        g_rowstart[i] = excl;
        g_cursor[i]   = excl;
    }
}

__global__ void fill_kernel(const int* __restrict__ erow, const int* __restrict__ ecol,
                            const float* __restrict__ evals) {
    int e = blockIdx.x * blockDim.x + threadIdx.x;
    if (e < NE) {
        int r = __ldg(&erow[e]);
        int pos = atomicAdd(&g_cursor[r], 1);
        g_packed[pos] = make_int2(__ldg(&ecol[e]), __float_as_int(__ldg(&evals[e])));
    }
}

// ---------------------------------------------------------------------------
// Pull: 2 rows per warp, 16 lanes per row, 4 features (4 halves = 8B) per lane.
// Per edge the 16-lane group reads 128B = ONE L2 line (half the fp32 traffic).
// fp32 accumulate, plain float4 store (bias fused, no atomics).
// ---------------------------------------------------------------------------
__global__ __launch_bounds__(256)
void pull_kernel(const float* __restrict__ bias, float* __restrict__ out) {
    int warp = (blockIdx.x * 256 + threadIdx.x) >> 5;
    if (warp >= NN / 2) return;
    int lane = threadIdx.x & 31;
    int half = lane >> 4;                // 0 or 1
    int sub  = lane & 15;                // 0..15

    const int row   = warp * 2 + half;
    const int start = g_rowstart[row];
    const int len   = g_counts[row];
    const int lenm  = max(len, __shfl_xor_sync(0xffffffffu, len, 16));
    const int2* __restrict__ plist = g_packed + start;
    const int fo = sub * 4;
    const int hb = half << 4;

    float4 acc = *(const float4*)&bias[fo];

    for (int base = 0; base < lenm; base += 16) {
        int m  = len - base;
        int mm = lenm - base; mm = mm < 16 ? mm : 16;
        int2 p = make_int2(0, 0);
        if (sub < m) p = plist[base + sub];

        int j = 0;
        for (; j + 4 <= mm; j += 4) {
            int c0 = __shfl_sync(0xffffffffu, p.x, hb + j + 0);
            int c1 = __shfl_sync(0xffffffffu, p.x, hb + j + 1);
            int c2 = __shfl_sync(0xffffffffu, p.x, hb + j + 2);
            int c3 = __shfl_sync(0xffffffffu, p.x, hb + j + 3);

            uint2 r0 = *(const uint2*)&g_support_h[(size_t)c0 * OUTF + fo];
            uint2 r1 = *(const uint2*)&g_support_h[(size_t)c1 * OUTF + fo];
            uint2 r2 = *(const uint2*)&g_support_h[(size_t)c2 * OUTF + fo];
            uint2 r3 = *(const uint2*)&g_support_h[(size_t)c3 * OUTF + fo];

            float v0 = __int_as_float(__shfl_sync(0xffffffffu, p.y, hb + j + 0));
            float v1 = __int_as_float(__shfl_sync(0xffffffffu, p.y, hb + j + 1));
            float v2 = __int_as_float(__shfl_sync(0xffffffffu, p.y, hb + j + 2));
            float v3 = __int_as_float(__shfl_sync(0xffffffffu, p.y, hb + j + 3));

            float2 a0 = __half22float2(*(__half2*)&r0.x), b0 = __half22float2(*(__half2*)&r0.y);
            float2 a1 = __half22float2(*(__half2*)&r1.x), b1 = __half22float2(*(__half2*)&r1.y);
            float2 a2 = __half22float2(*(__half2*)&r2.x), b2 = __half22float2(*(__half2*)&r2.y);
            float2 a3 = __half22float2(*(__half2*)&r3.x), b3 = __half22float2(*(__half2*)&r3.y);

            acc.x += a0.x * v0; acc.y += a0.y * v0; acc.z += b0.x * v0; acc.w += b0.y * v0;
            acc.x += a1.x * v1; acc.y += a1.y * v1; acc.z += b1.x * v1; acc.w += b1.y * v1;
            acc.x += a2.x * v2; acc.y += a2.y * v2; acc.z += b2.x * v2; acc.w += b2.y * v2;
            acc.x += a3.x * v3; acc.y += a3.y * v3; acc.z += b3.x * v3; acc.w += b3.y * v3;
        }
        for (; j < mm; j++) {
            int   c = __shfl_sync(0xffffffffu, p.x, hb + j);
            float v = __int_as_float(__shfl_sync(0xffffffffu, p.y, hb + j));
            uint2 rr = *(const uint2*)&g_support_h[(size_t)c * OUTF + fo];
            float2 aa = __half22float2(*(__half2*)&rr.x), bb = __half22float2(*(__half2*)&rr.y);
            acc.x += aa.x * v; acc.y += aa.y * v; acc.z += bb.x * v; acc.w += bb.y * v;
        }
    }

    *(float4*)&out[(size_t)row * OUTF + fo] = acc;
}

// ---------------------------------------------------------------------------
extern "C" void kernel_launch(void* const* d_in, const int* in_sizes, int n_in,
                              void* d_out, int out_size) {
    const float* x     = (const float*)d_in[0];   // [100000,128]
    const float* w     = (const float*)d_in[1];   // [128,64]
    const float* bias  = (const float*)d_in[2];   // [64]
    const int*   erow  = (const int*)  d_in[3];   // [1.6M]
    const int*   ecol  = (const int*)  d_in[4];   // [1.6M]
    const float* evals = (const float*)d_in[5];   // [1.6M]
    float* out = (float*)d_out;                   // [100000,64]

    const int n = in_sizes[0] / INF_;             // 100000

    // support = X @ W (fp32 compute, fp16 store) + zero counters/flags
    gemm_kernel<<<(n + 63) / 64, 256>>>(x, w, n);

    // Counting sort of edges by destination row
    hist_kernel<<<(NE + 255) / 256, 256>>>(erow);
    scan_kernel<<<NCHUNK, 512>>>();
    fill_kernel<<<(NE + 255) / 256, 256>>>(erow, ecol, evals);

    // Pull: out[row] = bias + sum(support[col] * val)
    {
        int warps = NN / 2;                        // 50000
        int blocks = (warps * 32 + 255) / 256;     // 6250
        pull_kernel<<<blocks, 256>>>(bias, out);
    }
}

// round 13
// speedup vs baseline: 1.1161x; 1.1161x over previous
#include <cuda_runtime.h>
#include <cuda_fp16.h>
#include <cstdint>

#define NN 100000
#define INF_ 128
#define OUTF 64
#define NE 1600000
#define NCHUNK ((NN + 511) / 512)   // 196

// Static device scratch (allocation-free per harness rules)
__device__ __half g_support_h[(size_t)NN * OUTF];  // 12.8 MB (fp16 gather path)
__device__ int    g_counts[NN];
__device__ int    g_rowstart[NN];
__device__ int    g_cursor[NN];
__device__ int    g_chunksum[NCHUNK];
__device__ int2   g_packed[NE];                    // 12.8 MB (col, val-bits) by row

// ---------------------------------------------------------------------------
// support = X @ W.  Tiled fp32 SIMT GEMM; epilogue stores fp16.
// Also zeroes g_counts (hist launches after this kernel in stream order).
// ---------------------------------------------------------------------------
__global__ __launch_bounds__(256, 2)
void gemm_kernel(const float* __restrict__ x, const float* __restrict__ w, int n) {
    __shared__ float xs[64][132];
    __shared__ float ws[128][68];

    const int tid  = threadIdx.x;
    const int brow = blockIdx.x * 64;

    // Fused: zero the histogram counters
    {
        int gi = blockIdx.x * 256 + tid;
        if (gi < NN) g_counts[gi] = 0;
    }

#pragma unroll
    for (int it = 0; it < 8; it++) {
        int i = tid + it * 256;
        int k = i >> 4;
        int c = (i & 15) << 2;
        float4 v = *(const float4*)&w[k * OUTF + c];
        *(float4*)&ws[k][c] = v;
    }
#pragma unroll
    for (int it = 0; it < 8; it++) {
        int i = tid + it * 256;
        int r = i >> 5;
        int k = (i & 31) << 2;
        int grow = brow + r;
        float4 v = make_float4(0.f, 0.f, 0.f, 0.f);
        if (grow < n) v = *(const float4*)&x[(size_t)grow * INF_ + k];
        *(float4*)&xs[r][k] = v;
    }
    __syncthreads();

    const int r0 = (tid >> 4) << 2;
    const int c0 = (tid & 15) << 2;

    float acc[4][4] = {};
#pragma unroll 4
    for (int k = 0; k < 128; k++) {
        float a0 = xs[r0 + 0][k];
        float a1 = xs[r0 + 1][k];
        float a2 = xs[r0 + 2][k];
        float a3 = xs[r0 + 3][k];
        float4 b = *(float4*)&ws[k][c0];
        acc[0][0] += a0 * b.x; acc[0][1] += a0 * b.y; acc[0][2] += a0 * b.z; acc[0][3] += a0 * b.w;
        acc[1][0] += a1 * b.x; acc[1][1] += a1 * b.y; acc[1][2] += a1 * b.z; acc[1][3] += a1 * b.w;
        acc[2][0] += a2 * b.x; acc[2][1] += a2 * b.y; acc[2][2] += a2 * b.z; acc[2][3] += a2 * b.w;
        acc[3][0] += a3 * b.x; acc[3][1] += a3 * b.y; acc[3][2] += a3 * b.z; acc[3][3] += a3 * b.w;
    }

#pragma unroll
    for (int i = 0; i < 4; i++) {
        int grow = brow + r0 + i;
        if (grow < n) {
            __half2 h0 = __floats2half2_rn(acc[i][0], acc[i][1]);
            __half2 h1 = __floats2half2_rn(acc[i][2], acc[i][3]);
            uint2 u = make_uint2(*(unsigned*)&h0, *(unsigned*)&h1);
            *(uint2*)&g_support_h[(size_t)grow * OUTF + c0] = u;
        }
    }
}

// ---------------------------------------------------------------------------
// Build phase: counting sort of edges by destination row
// ---------------------------------------------------------------------------
__global__ void hist_kernel(const int* __restrict__ erow) {
    int e = blockIdx.x * blockDim.x + threadIdx.x;
    if (e < NE) atomicAdd(&g_counts[__ldg(&erow[e])], 1);
}

// S1: per-chunk (512) reduction of counts -> g_chunksum[b]
__global__ __launch_bounds__(512)
void scan1_kernel() {
    __shared__ int s[512];
    int t = threadIdx.x, b = blockIdx.x;
    int i = b * 512 + t;
    s[t] = (i < NN) ? g_counts[i] : 0;
    __syncthreads();
#pragma unroll
    for (int off = 256; off > 0; off >>= 1) {
        if (t < off) s[t] += s[t + off];
        __syncthreads();
    }
    if (t == 0) g_chunksum[b] = s[0];
}

// S3: per-chunk exclusive scan; chunk base computed inline via warp reduction
// over chunksum[0..b-1] (196 tiny L2-hot loads).
__global__ __launch_bounds__(512)
void scan3_kernel() {
    __shared__ int s[512];
    __shared__ int sbase[1];
    int t = threadIdx.x, b = blockIdx.x;
    int i = b * 512 + t;
    int v = (i < NN) ? g_counts[i] : 0;
    s[t] = v;

    if (t < 32) {
        int part = 0;
        for (int c = t; c < b; c += 32) part += g_chunksum[c];
#pragma unroll
        for (int off = 16; off > 0; off >>= 1)
            part += __shfl_xor_sync(0xffffffffu, part, off);
        if (t == 0) sbase[0] = part;
    }
    __syncthreads();
#pragma unroll
    for (int off = 1; off < 512; off <<= 1) {
        int a = (t >= off) ? s[t - off] : 0;
        __syncthreads();
        s[t] += a;
        __syncthreads();
    }
    if (i < NN) {
        int excl = s[t] - v + sbase[0];
        g_rowstart[i] = excl;
        g_cursor[i]   = excl;
    }
}

__global__ void fill_kernel(const int* __restrict__ erow, const int* __restrict__ ecol,
                            const float* __restrict__ evals) {
    int e = blockIdx.x * blockDim.x + threadIdx.x;
    if (e < NE) {
        int r = __ldg(&erow[e]);
        int pos = atomicAdd(&g_cursor[r], 1);
        g_packed[pos] = make_int2(__ldg(&ecol[e]), __float_as_int(__ldg(&evals[e])));
    }
}

// ---------------------------------------------------------------------------
// Pull: 2 rows per warp, 16 lanes per row, 4 features (4 halves = 8B) per lane.
// Per edge the 16-lane group reads 128B = ONE L2 line.
// fp32 accumulate, plain float4 store (bias fused, no atomics).
// ---------------------------------------------------------------------------
__global__ __launch_bounds__(256)
void pull_kernel(const float* __restrict__ bias, float* __restrict__ out) {
    int warp = (blockIdx.x * 256 + threadIdx.x) >> 5;
    if (warp >= NN / 2) return;
    int lane = threadIdx.x & 31;
    int half = lane >> 4;                // 0 or 1
    int sub  = lane & 15;                // 0..15

    const int row   = warp * 2 + half;
    const int start = g_rowstart[row];
    const int len   = g_counts[row];
    const int lenm  = max(len, __shfl_xor_sync(0xffffffffu, len, 16));
    const int2* __restrict__ plist = g_packed + start;
    const int fo = sub * 4;
    const int hb = half << 4;

    float4 acc = *(const float4*)&bias[fo];

    for (int base = 0; base < lenm; base += 16) {
        int m  = len - base;
        int mm = lenm - base; mm = mm < 16 ? mm : 16;
        int2 p = make_int2(0, 0);
        if (sub < m) p = plist[base + sub];

        int j = 0;
        for (; j + 4 <= mm; j += 4) {
            int c0 = __shfl_sync(0xffffffffu, p.x, hb + j + 0);
            int c1 = __shfl_sync(0xffffffffu, p.x, hb + j + 1);
            int c2 = __shfl_sync(0xffffffffu, p.x, hb + j + 2);
            int c3 = __shfl_sync(0xffffffffu, p.x, hb + j + 3);

            uint2 r0 = *(const uint2*)&g_support_h[(size_t)c0 * OUTF + fo];
            uint2 r1 = *(const uint2*)&g_support_h[(size_t)c1 * OUTF + fo];
            uint2 r2 = *(const uint2*)&g_support_h[(size_t)c2 * OUTF + fo];
            uint2 r3 = *(const uint2*)&g_support_h[(size_t)c3 * OUTF + fo];

            float v0 = __int_as_float(__shfl_sync(0xffffffffu, p.y, hb + j + 0));
            float v1 = __int_as_float(__shfl_sync(0xffffffffu, p.y, hb + j + 1));
            float v2 = __int_as_float(__shfl_sync(0xffffffffu, p.y, hb + j + 2));
            float v3 = __int_as_float(__shfl_sync(0xffffffffu, p.y, hb + j + 3));

            float2 a0 = __half22float2(*(__half2*)&r0.x), b0 = __half22float2(*(__half2*)&r0.y);
            float2 a1 = __half22float2(*(__half2*)&r1.x), b1 = __half22float2(*(__half2*)&r1.y);
            float2 a2 = __half22float2(*(__half2*)&r2.x), b2 = __half22float2(*(__half2*)&r2.y);
            float2 a3 = __half22float2(*(__half2*)&r3.x), b3 = __half22float2(*(__half2*)&r3.y);

            acc.x += a0.x * v0; acc.y += a0.y * v0; acc.z += b0.x * v0; acc.w += b0.y * v0;
            acc.x += a1.x * v1; acc.y += a1.y * v1; acc.z += b1.x * v1; acc.w += b1.y * v1;
            acc.x += a2.x * v2; acc.y += a2.y * v2; acc.z += b2.x * v2; acc.w += b2.y * v2;
            acc.x += a3.x * v3; acc.y += a3.y * v3; acc.z += b3.x * v3; acc.w += b3.y * v3;
        }
        for (; j < mm; j++) {
            int   c = __shfl_sync(0xffffffffu, p.x, hb + j);
            float v = __int_as_float(__shfl_sync(0xffffffffu, p.y, hb + j));
            uint2 rr = *(const uint2*)&g_support_h[(size_t)c * OUTF + fo];
            float2 aa = __half22float2(*(__half2*)&rr.x), bb = __half22float2(*(__half2*)&rr.y);
            acc.x += aa.x * v; acc.y += aa.y * v; acc.z += bb.x * v; acc.w += bb.y * v;
        }
    }

    *(float4*)&out[(size_t)row * OUTF + fo] = acc;
}

// ---------------------------------------------------------------------------
extern "C" void kernel_launch(void* const* d_in, const int* in_sizes, int n_in,
                              void* d_out, int out_size) {
    const float* x     = (const float*)d_in[0];   // [100000,128]
    const float* w     = (const float*)d_in[1];   // [128,64]
    const float* bias  = (const float*)d_in[2];   // [64]
    const int*   erow  = (const int*)  d_in[3];   // [1.6M]
    const int*   ecol  = (const int*)  d_in[4];   // [1.6M]
    const float* evals = (const float*)d_in[5];   // [1.6M]
    float* out = (float*)d_out;                   // [100000,64]

    const int n = in_sizes[0] / INF_;             // 100000

    // support = X @ W (fp32 compute, fp16 store) + zero counters
    gemm_kernel<<<(n + 63) / 64, 256>>>(x, w, n);

    // Counting sort of edges by destination row
    hist_kernel<<<(NE + 255) / 256, 256>>>(erow);
    scan1_kernel<<<NCHUNK, 512>>>();
    scan3_kernel<<<NCHUNK, 512>>>();
    fill_kernel<<<(NE + 255) / 256, 256>>>(erow, ecol, evals);

    // Pull: out[row] = bias + sum(support[col] * val)
    {
        int warps = NN / 2;                        // 50000
        int blocks = (warps * 32 + 255) / 256;     // 6250
        pull_kernel<<<blocks, 256>>>(bias, out);
    }
}

// round 14
// speedup vs baseline: 1.1235x; 1.0066x over previous
#include <cuda_runtime.h>
#include <cuda_fp16.h>
#include <cstdint>

#define NN 100000
#define INF_ 128
#define OUTF 64
#define NE 1600000
#define NCHUNK ((NN + 511) / 512)   // 196

// Static device scratch (allocation-free per harness rules)
__device__ __half g_support_h[(size_t)NN * OUTF];  // 12.8 MB (fp16 gather path)
__device__ int    g_counts[NN];
__device__ int    g_rowstart[NN];
__device__ int    g_cursor[NN];
__device__ int    g_chunksum[NCHUNK];
__device__ int2   g_packed[NE];                    // 12.8 MB (col, val-bits) by row

// ---------------------------------------------------------------------------
// support = X @ W.  Tiled fp32 SIMT GEMM; epilogue stores fp16.
// Also zeroes g_counts (hist launches after this kernel in stream order).
// ---------------------------------------------------------------------------
__global__ __launch_bounds__(256, 2)
void gemm_kernel(const float* __restrict__ x, const float* __restrict__ w, int n) {
    __shared__ float xs[64][132];
    __shared__ float ws[128][68];

    const int tid  = threadIdx.x;
    const int brow = blockIdx.x * 64;

    // Fused: zero the histogram counters
    {
        int gi = blockIdx.x * 256 + tid;
        if (gi < NN) g_counts[gi] = 0;
    }

#pragma unroll
    for (int it = 0; it < 8; it++) {
        int i = tid + it * 256;
        int k = i >> 4;
        int c = (i & 15) << 2;
        float4 v = *(const float4*)&w[k * OUTF + c];
        *(float4*)&ws[k][c] = v;
    }
#pragma unroll
    for (int it = 0; it < 8; it++) {
        int i = tid + it * 256;
        int r = i >> 5;
        int k = (i & 31) << 2;
        int grow = brow + r;
        float4 v = make_float4(0.f, 0.f, 0.f, 0.f);
        if (grow < n) v = *(const float4*)&x[(size_t)grow * INF_ + k];
        *(float4*)&xs[r][k] = v;
    }
    __syncthreads();

    const int r0 = (tid >> 4) << 2;
    const int c0 = (tid & 15) << 2;

    float acc[4][4] = {};
#pragma unroll 4
    for (int k = 0; k < 128; k++) {
        float a0 = xs[r0 + 0][k];
        float a1 = xs[r0 + 1][k];
        float a2 = xs[r0 + 2][k];
        float a3 = xs[r0 + 3][k];
        float4 b = *(float4*)&ws[k][c0];
        acc[0][0] += a0 * b.x; acc[0][1] += a0 * b.y; acc[0][2] += a0 * b.z; acc[0][3] += a0 * b.w;
        acc[1][0] += a1 * b.x; acc[1][1] += a1 * b.y; acc[1][2] += a1 * b.z; acc[1][3] += a1 * b.w;
        acc[2][0] += a2 * b.x; acc[2][1] += a2 * b.y; acc[2][2] += a2 * b.z; acc[2][3] += a2 * b.w;
        acc[3][0] += a3 * b.x; acc[3][1] += a3 * b.y; acc[3][2] += a3 * b.z; acc[3][3] += a3 * b.w;
    }

#pragma unroll
    for (int i = 0; i < 4; i++) {
        int grow = brow + r0 + i;
        if (grow < n) {
            __half2 h0 = __floats2half2_rn(acc[i][0], acc[i][1]);
            __half2 h1 = __floats2half2_rn(acc[i][2], acc[i][3]);
            uint2 u = make_uint2(*(unsigned*)&h0, *(unsigned*)&h1);
            *(uint2*)&g_support_h[(size_t)grow * OUTF + c0] = u;
        }
    }
}

// ---------------------------------------------------------------------------
// Build phase: counting sort of edges by destination row.
// hist/fill process 4 edges per thread (vector loads, 4 independent atomics
// in flight) to hide the ~318-cyc L2 atomic latency.
// ---------------------------------------------------------------------------
__global__ void hist_kernel(const int4* __restrict__ erow4) {
    int i = blockIdx.x * blockDim.x + threadIdx.x;
    if (i < NE / 4) {
        int4 r = __ldg(&erow4[i]);
        atomicAdd(&g_counts[r.x], 1);
        atomicAdd(&g_counts[r.y], 1);
        atomicAdd(&g_counts[r.z], 1);
        atomicAdd(&g_counts[r.w], 1);
    }
}

// S1: per-chunk (512) reduction of counts -> g_chunksum[b]
__global__ __launch_bounds__(512)
void scan1_kernel() {
    __shared__ int s[512];
    int t = threadIdx.x, b = blockIdx.x;
    int i = b * 512 + t;
    s[t] = (i < NN) ? g_counts[i] : 0;
    __syncthreads();
#pragma unroll
    for (int off = 256; off > 0; off >>= 1) {
        if (t < off) s[t] += s[t + off];
        __syncthreads();
    }
    if (t == 0) g_chunksum[b] = s[0];
}

// S3: per-chunk exclusive scan; chunk base computed inline via warp reduction
// over chunksum[0..b-1] (196 tiny L2-hot loads).
__global__ __launch_bounds__(512)
void scan3_kernel() {
    __shared__ int s[512];
    __shared__ int sbase[1];
    int t = threadIdx.x, b = blockIdx.x;
    int i = b * 512 + t;
    int v = (i < NN) ? g_counts[i] : 0;
    s[t] = v;

    if (t < 32) {
        int part = 0;
        for (int c = t; c < b; c += 32) part += g_chunksum[c];
#pragma unroll
        for (int off = 16; off > 0; off >>= 1)
            part += __shfl_xor_sync(0xffffffffu, part, off);
        if (t == 0) sbase[0] = part;
    }
    __syncthreads();
#pragma unroll
    for (int off = 1; off < 512; off <<= 1) {
        int a = (t >= off) ? s[t - off] : 0;
        __syncthreads();
        s[t] += a;
        __syncthreads();
    }
    if (i < NN) {
        int excl = s[t] - v + sbase[0];
        g_rowstart[i] = excl;
        g_cursor[i]   = excl;
    }
}

__global__ void fill_kernel(const int4* __restrict__ erow4, const int4* __restrict__ ecol4,
                            const float4* __restrict__ evals4) {
    int i = blockIdx.x * blockDim.x + threadIdx.x;
    if (i < NE / 4) {
        int4   r = __ldg(&erow4[i]);
        int4   c = __ldg(&ecol4[i]);
        float4 v = __ldg(&evals4[i]);
        // 4 independent atomics in flight
        int p0 = atomicAdd(&g_cursor[r.x], 1);
        int p1 = atomicAdd(&g_cursor[r.y], 1);
        int p2 = atomicAdd(&g_cursor[r.z], 1);
        int p3 = atomicAdd(&g_cursor[r.w], 1);
        g_packed[p0] = make_int2(c.x, __float_as_int(v.x));
        g_packed[p1] = make_int2(c.y, __float_as_int(v.y));
        g_packed[p2] = make_int2(c.z, __float_as_int(v.z));
        g_packed[p3] = make_int2(c.w, __float_as_int(v.w));
    }
}

// ---------------------------------------------------------------------------
// Pull: 2 rows per warp, 16 lanes per row, 4 features (8B fp16) per lane.
// Per edge the 16-lane group reads 128B = ONE L2 line.
// Inner loop MLP=8: eight independent gathers in flight per thread.
// fp32 accumulate, plain float4 store (bias fused, no atomics).
// ---------------------------------------------------------------------------
__global__ __launch_bounds__(256)
void pull_kernel(const float* __restrict__ bias, float* __restrict__ out) {
    int warp = (blockIdx.x * 256 + threadIdx.x) >> 5;
    if (warp >= NN / 2) return;
    int lane = threadIdx.x & 31;
    int half = lane >> 4;                // 0 or 1
    int sub  = lane & 15;                // 0..15

    const int row   = warp * 2 + half;
    const int start = g_rowstart[row];
    const int len   = g_counts[row];
    const int lenm  = max(len, __shfl_xor_sync(0xffffffffu, len, 16));
    const int2* __restrict__ plist = g_packed + start;
    const int fo = sub * 4;
    const int hb = half << 4;

    float4 acc = *(const float4*)&bias[fo];

    for (int base = 0; base < lenm; base += 16) {
        int m  = len - base;
        int mm = lenm - base; mm = mm < 16 ? mm : 16;
        int2 p = make_int2(0, 0);
        if (sub < m) p = plist[base + sub];

        int j = 0;
        for (; j + 8 <= mm; j += 8) {
            int cc[8];
            uint2 rr[8];
            float vv[8];
#pragma unroll
            for (int k = 0; k < 8; k++)
                cc[k] = __shfl_sync(0xffffffffu, p.x, hb + j + k);
#pragma unroll
            for (int k = 0; k < 8; k++)
                rr[k] = *(const uint2*)&g_support_h[(size_t)cc[k] * OUTF + fo];
#pragma unroll
            for (int k = 0; k < 8; k++)
                vv[k] = __int_as_float(__shfl_sync(0xffffffffu, p.y, hb + j + k));
#pragma unroll
            for (int k = 0; k < 8; k++) {
                float2 a = __half22float2(*(__half2*)&rr[k].x);
                float2 b = __half22float2(*(__half2*)&rr[k].y);
                acc.x += a.x * vv[k]; acc.y += a.y * vv[k];
                acc.z += b.x * vv[k]; acc.w += b.y * vv[k];
            }
        }
        for (; j + 4 <= mm; j += 4) {
            int cc[4];
            uint2 rr[4];
            float vv[4];
#pragma unroll
            for (int k = 0; k < 4; k++)
                cc[k] = __shfl_sync(0xffffffffu, p.x, hb + j + k);
#pragma unroll
            for (int k = 0; k < 4; k++)
                rr[k] = *(const uint2*)&g_support_h[(size_t)cc[k] * OUTF + fo];
#pragma unroll
            for (int k = 0; k < 4; k++)
                vv[k] = __int_as_float(__shfl_sync(0xffffffffu, p.y, hb + j + k));
#pragma unroll
            for (int k = 0; k < 4; k++) {
                float2 a = __half22float2(*(__half2*)&rr[k].x);
                float2 b = __half22float2(*(__half2*)&rr[k].y);
                acc.x += a.x * vv[k]; acc.y += a.y * vv[k];
                acc.z += b.x * vv[k]; acc.w += b.y * vv[k];
            }
        }
        for (; j < mm; j++) {
            int   c = __shfl_sync(0xffffffffu, p.x, hb + j);
            float v = __int_as_float(__shfl_sync(0xffffffffu, p.y, hb + j));
            uint2 rv = *(const uint2*)&g_support_h[(size_t)c * OUTF + fo];
            float2 a = __half22float2(*(__half2*)&rv.x);
            float2 b = __half22float2(*(__half2*)&rv.y);
            acc.x += a.x * v; acc.y += a.y * v; acc.z += b.x * v; acc.w += b.y * v;
        }
    }

    *(float4*)&out[(size_t)row * OUTF + fo] = acc;
}

// ---------------------------------------------------------------------------
extern "C" void kernel_launch(void* const* d_in, const int* in_sizes, int n_in,
                              void* d_out, int out_size) {
    const float* x     = (const float*)d_in[0];   // [100000,128]
    const float* w     = (const float*)d_in[1];   // [128,64]
    const float* bias  = (const float*)d_in[2];   // [64]
    const int*   erow  = (const int*)  d_in[3];   // [1.6M]
    const int*   ecol  = (const int*)  d_in[4];   // [1.6M]
    const float* evals = (const float*)d_in[5];   // [1.6M]
    float* out = (float*)d_out;                   // [100000,64]

    const int n = in_sizes[0] / INF_;             // 100000

    // support = X @ W (fp32 compute, fp16 store) + zero counters
    gemm_kernel<<<(n + 63) / 64, 256>>>(x, w, n);

    // Counting sort of edges by destination row (4 edges/thread ILP)
    hist_kernel<<<(NE / 4 + 255) / 256, 256>>>((const int4*)erow);
    scan1_kernel<<<NCHUNK, 512>>>();
    scan3_kernel<<<NCHUNK, 512>>>();
    fill_kernel<<<(NE / 4 + 255) / 256, 256>>>((const int4*)erow, (const int4*)ecol,
                                               (const float4*)evals);

    // Pull: out[row] = bias + sum(support[col] * val)
    {
        int warps = NN / 2;                        // 50000
        int blocks = (warps * 32 + 255) / 256;     // 6250
        pull_kernel<<<blocks, 256>>>(bias, out);
    }
}